// round 1
// baseline (speedup 1.0000x reference)
#include <cuda_runtime.h>

// Grouped conv: x (1,48,56,56) f32, w (24,96,7) f32, shift (int scalar).
// wt[oc][ic][kw] = w[ic][oc][kw]; out[g*96+oc][h+shift mod 56][w] =
//   sum_{ic<24,kw<7} x[g*24+ic][h][w+kw-3] * wt[oc][ic][kw]
//
// One block = (oc, group, row-half). 112 active threads: 28 rows x 4 w-tiles
// of 14 outputs each. Weights for this oc staged in smem (168 floats).

#define Hdim 56
#define Wdim 56
#define ICg  24
#define OCG  96
#define KW   7
#define PADW 3
#define WT   14   // outputs per thread along w
#define NWT  4    // w-tiles per row (4*14 = 56)
#define RPB  28   // rows per block
#define NACT (RPB*NWT)   // 112 active threads

__global__ __launch_bounds__(128, 8)
void conv1x7_grouped_kernel(const float* __restrict__ x,
                            const float* __restrict__ w,
                            const int*   __restrict__ shift,
                            float*       __restrict__ out)
{
    __shared__ float sw[ICg * KW];

    const int oc = blockIdx.x;   // 0..95
    const int g  = blockIdx.y;   // 0..1
    const int rb = blockIdx.z;   // 0..1
    const int tid = threadIdx.x;

    // Stage weights for this output channel: sw[ic*7+kw] = w[ic*672 + oc*7 + kw]
    for (int i = tid; i < ICg * KW; i += blockDim.x) {
        int ic = i / KW;
        int kw = i - ic * KW;
        sw[i] = w[ic * (OCG * KW) + oc * KW + kw];
    }
    __syncthreads();

    if (tid >= NACT) return;

    const int h  = rb * RPB + (tid >> 2);
    const int wt = tid & 3;
    const int w0 = wt * WT;

    const float* xg = x + (size_t)g * ICg * Hdim * Wdim + h * Wdim;

    float acc[WT];
    #pragma unroll
    for (int i = 0; i < WT; i++) acc[i] = 0.f;

    #pragma unroll 1
    for (int ic = 0; ic < ICg; ic++) {
        float wv[KW];
        #pragma unroll
        for (int k = 0; k < KW; k++) wv[k] = sw[ic * KW + k];

        const float* xr = xg + ic * (Hdim * Wdim);
        float xv[WT + KW - 1];   // 20-wide window [w0-3, w0+17)
        #pragma unroll
        for (int j = 0; j < WT + KW - 1; j++) {
            int gw = w0 - PADW + j;
            xv[j] = (gw >= 0 && gw < Wdim) ? xr[gw] : 0.f;
        }

        #pragma unroll
        for (int i = 0; i < WT; i++) {
            #pragma unroll
            for (int k = 0; k < KW; k++) {
                acc[i] = fmaf(xv[i + k], wv[k], acc[i]);
            }
        }
    }

    // Roll along H by shift (read low 32 bits; safe for int32/int64 scalar).
    const int s  = *shift;
    int ho = (h + s) % Hdim;
    if (ho < 0) ho += Hdim;

    float* o = out + (size_t)(g * OCG + oc) * Hdim * Wdim + ho * Wdim + w0;
    #pragma unroll
    for (int i = 0; i < WT; i++) o[i] = acc[i];
}

extern "C" void kernel_launch(void* const* d_in, const int* in_sizes, int n_in,
                              void* d_out, int out_size)
{
    const float* x     = (const float*)d_in[0];
    const float* w     = (const float*)d_in[1];
    const int*   shift = (const int*)  d_in[2];
    float*       out   = (float*)d_out;

    dim3 grid(OCG, 2, Hdim / RPB);   // 96 x 2 x 2 = 384 blocks
    conv1x7_grouped_kernel<<<grid, 128>>>(x, w, shift, out);
}

// round 2
// speedup vs baseline: 1.6366x; 1.6366x over previous
#include <cuda_runtime.h>

// Grouped 1x7 conv (NCHW, groups=2, identical weights per group) + roll(H).
// x: (1,48,56,56) f32, w: (24,96,7) f32, shift: int. out: (1,192,56,56) f32.
// wt[oc][ic][kw] = w[ic][oc][kw];
// out[g*96+oc][(h+shift)%56][w] = sum_{ic,kw} x[g*24+ic][h][w+kw-3] * wt[oc][ic][kw]
//
// Tile: 1 thread = 8 w-outputs x 2 oc (16 acc). 37632 threads = 147 blocks x 256.
// x window per ic loaded as 5 aligned float4 (2 boundary predicates only).
// Weights for the block's 2 oc-pairs staged in smem, read as float2 broadcast.

#define Hdim 56
#define Wdim 56
#define HW   3136
#define ICg  24
#define KW   7

__global__ __launch_bounds__(256, 1)
void conv1x7_k2(const float* __restrict__ x, const float* __restrict__ w,
                const int* __restrict__ shift, float* __restrict__ out)
{
    __shared__ float sw[2 * ICg * KW * 2];   // [pi][ic][kw][j] = 672 floats

    const int tid = threadIdx.x;
    const int id  = blockIdx.x * 256 + tid;

    // first combined channel index (c = g*48 + ocpair) touched by this block
    const int c0 = (blockIdx.x * 256) / 392;

    // Stage weights for combined channels c0 and c0+1.
    // sw[pi*336 + ic*14 + kw*2 + j] = w[ic][2*((c0+pi)%48)+j][kw]
    for (int i = tid; i < 672; i += 256) {
        int pi = i / 336;
        int r  = i - pi * 336;
        int ic = r / 14;
        int r2 = r - ic * 14;
        int kw = r2 >> 1;
        int j  = r2 & 1;
        int c  = min(c0 + pi, 95);
        int oc = 2 * (c % 48) + j;
        sw[i] = w[ic * 672 + oc * 7 + kw];
    }
    __syncthreads();

    const int wt = id % 7;          // w-tile 0..6 (w0 = 8*wt)
    int t = id / 7;
    const int h = t % 56;
    t = t / 56;                     // combined c = g*48 + ocp, 0..95
    const int g   = t / 48;
    const int ocp = t - g * 48;
    const int pi  = t - c0;         // 0 or 1

    const int w0  = wt * 8;
    const bool pLo = (wt != 0);     // f4[0] covers w0-4..w0-1 (pad when wt==0)
    const bool pHi = (wt != 6);     // f4[3],f4[4] cover w0+8..w0+15 (pad when wt==6)

    const float*  xrow0 = x + (size_t)g * (ICg * HW) + h * Wdim + (w0 - 4);
    const float2* swp   = (const float2*)(sw + pi * 336);

    float acc[2][8];
    #pragma unroll
    for (int j = 0; j < 2; j++)
        #pragma unroll
        for (int i = 0; i < 8; i++) acc[j][i] = 0.f;

    const float4 z4 = make_float4(0.f, 0.f, 0.f, 0.f);

    #pragma unroll 4
    for (int ic = 0; ic < ICg; ic++) {
        const float4* xp = (const float4*)(xrow0 + ic * HW);
        float4 v0 = pLo ? xp[0] : z4;
        float4 v1 = xp[1];
        float4 v2 = xp[2];
        float4 v3 = pHi ? xp[3] : z4;
        float4 v4 = pHi ? xp[4] : z4;

        float xv[20];
        *(float4*)(xv +  0) = v0;
        *(float4*)(xv +  4) = v1;
        *(float4*)(xv +  8) = v2;
        *(float4*)(xv + 12) = v3;
        *(float4*)(xv + 16) = v4;

        float2 wv[KW];
        #pragma unroll
        for (int k = 0; k < KW; k++) wv[k] = swp[ic * KW + k];

        #pragma unroll
        for (int i = 0; i < 8; i++) {
            #pragma unroll
            for (int k = 0; k < KW; k++) {
                // xv[j] holds x at w = w0-4+j; need w0+i+k-3 -> j = 1+i+k
                acc[0][i] = fmaf(xv[1 + i + k], wv[k].x, acc[0][i]);
                acc[1][i] = fmaf(xv[1 + i + k], wv[k].y, acc[1][i]);
            }
        }
    }

    // roll along H
    const int s = *shift;
    int ho = (h + s) % Hdim;
    if (ho < 0) ho += Hdim;

    #pragma unroll
    for (int j = 0; j < 2; j++) {
        float* o = out + (size_t)(g * 96 + 2 * ocp + j) * HW + ho * Wdim + w0;
        ((float4*)o)[0] = make_float4(acc[j][0], acc[j][1], acc[j][2], acc[j][3]);
        ((float4*)o)[1] = make_float4(acc[j][4], acc[j][5], acc[j][6], acc[j][7]);
    }
}

extern "C" void kernel_launch(void* const* d_in, const int* in_sizes, int n_in,
                              void* d_out, int out_size)
{
    const float* x     = (const float*)d_in[0];
    const float* w     = (const float*)d_in[1];
    const int*   shift = (const int*)  d_in[2];
    float*       out   = (float*)d_out;

    // 2 groups * 48 ocpairs * 56 rows * 7 wtiles = 37632 threads = 147 * 256
    conv1x7_k2<<<147, 256>>>(x, w, shift, out);
}